// round 3
// baseline (speedup 1.0000x reference)
#include <cuda_runtime.h>
#include <math.h>

#define B_  32
#define T0_ 2048
#define T1_ 2044
#define T2_ 2040
#define T3_ 2034

typedef unsigned long long u64;

// ---------------- scratch (device globals; no allocations allowed) ----------
__device__ float g_xT  [20   * B_ * T0_];
__device__ float g_act1[512  * B_ * T1_];
__device__ float g_act2[512  * B_ * T2_];
__device__ float g_act3[512  * B_ * T3_];
__device__ float g_act4[512  * B_ * T3_];
__device__ float g_act5[1500 * B_ * T3_];
__device__ float g_scl [1500];
__device__ float g_shf [1500];
__device__ float g_pool[B_ * 3000];
__device__ float g_y1  [B_ * 512];
__device__ float g_y2  [B_ * 512];

// ---------------- transpose x[b][t][f] -> xT[f][b][t] -----------------------
__global__ void transpose_x(const float* __restrict__ x, float* __restrict__ xT) {
    int idx = blockIdx.x * blockDim.x + threadIdx.x;
    const int total = B_ * T0_ * 20;
    if (idx >= total) return;
    int f = idx % 20;
    int t = (idx / 20) % T0_;
    int b = idx / (20 * T0_);
    xT[((size_t)f * B_ + b) * T0_ + t] = x[idx];
}

// ---------------- fused (bn-affine on input) + splice + 1x1 conv GEMM --------
// Y[m][b][t] = act( sum_k W[m][k] * (sA[f]*X[f][b][t+off] + sB[f]) + bias[m] )
//   k = f*C + c,  off = c*offStride.  X layout [F][B][Tin], Y layout [M][B][Tout].
// Inner product runs on packed fp32x2 FMA (FFMA2).
#define TBM 128
#define TBN 128
#define TBK 16

__global__ __launch_bounds__(256)
void gemm_splice(const float* __restrict__ W, const float* __restrict__ bias,
                 const float* __restrict__ X, float* __restrict__ Y,
                 const float* __restrict__ scl, const float* __restrict__ shf,
                 int M, int K, int C, int offStride,
                 int Tin, int Tout, int actMode)
{
    __shared__ float As2[TBK][2 * TBM];  // A values duplicated: (a,a) pairs
    __shared__ float Bs [TBK][TBN];

    const int b     = blockIdx.z;
    const int m0    = blockIdx.y * TBM;
    const int tbase = blockIdx.x * TBN;
    const int tid   = threadIdx.x;
    const int tx    = tid & 15;
    const int ty    = tid >> 4;

    const float* Xb = X + (size_t)b * Tin;

    u64 acc[8][4];
#pragma unroll
    for (int i = 0; i < 8; i++)
#pragma unroll
        for (int j = 0; j < 4; j++) acc[i][j] = 0ULL;

    const int aRow  = tid >> 1;         // 0..127
    const int aCol0 = (tid & 1) * 8;    // 0 or 8
    const int bRow  = tid >> 4;         // 0..15
    const int bCol0 = (tid & 15) * 8;   // 0..120

    for (int k0 = 0; k0 < K; k0 += TBK) {
        // ---- load W tile, duplicated (zero-padded at K / M edges) ----
        {
            int m = m0 + aRow;
#pragma unroll
            for (int j = 0; j < 8; j++) {
                int k = k0 + aCol0 + j;
                float v = (k < K && m < M) ? W[(size_t)m * K + k] : 0.f;
                *(float2*)&As2[aCol0 + j][2 * aRow] = make_float2(v, v);
            }
        }
        // ---- load X tile with splice gather + folded bn affine ----
        {
            int k = k0 + bRow;
            bool kv = (k < K);
            int f = 0, off = 0;
            if (kv) { f = k / C; off = (k - f * C) * offStride; }
            float sA = 1.f, sB = 0.f;
            if (kv && scl) { sA = scl[f]; sB = shf[f]; }
            const float* src = Xb + (size_t)f * (B_ * (size_t)Tin) + off + tbase + bCol0;
#pragma unroll
            for (int j = 0; j < 8; j++) {
                int t = tbase + bCol0 + j;
                Bs[bRow][bCol0 + j] = (kv && t < Tout) ? fmaf(src[j], sA, sB) : 0.f;
            }
        }
        __syncthreads();

#pragma unroll
        for (int kk = 0; kk < TBK; kk++) {
            u64 a_pk[8], b_pk[4];
            {
                ulonglong2 t0 = *(const ulonglong2*)&As2[kk][ty * 16 + 0];
                ulonglong2 t1 = *(const ulonglong2*)&As2[kk][ty * 16 + 4];
                ulonglong2 t2 = *(const ulonglong2*)&As2[kk][ty * 16 + 8];
                ulonglong2 t3 = *(const ulonglong2*)&As2[kk][ty * 16 + 12];
                a_pk[0] = t0.x; a_pk[1] = t0.y; a_pk[2] = t1.x; a_pk[3] = t1.y;
                a_pk[4] = t2.x; a_pk[5] = t2.y; a_pk[6] = t3.x; a_pk[7] = t3.y;
            }
            {
                ulonglong2 u0 = *(const ulonglong2*)&Bs[kk][tx * 8 + 0];
                ulonglong2 u1 = *(const ulonglong2*)&Bs[kk][tx * 8 + 4];
                b_pk[0] = u0.x; b_pk[1] = u0.y; b_pk[2] = u1.x; b_pk[3] = u1.y;
            }
#pragma unroll
            for (int i = 0; i < 8; i++)
#pragma unroll
                for (int j = 0; j < 4; j++)
                    asm volatile("fma.rn.f32x2 %0, %1, %2, %0;"
                                 : "+l"(acc[i][j]) : "l"(a_pk[i]), "l"(b_pk[j]));
        }
        __syncthreads();
    }

    const size_t strideY = (size_t)B_ * Tout;
#pragma unroll
    for (int i = 0; i < 8; i++) {
        int m = m0 + ty * 8 + i;
        if (m >= M) continue;
        float bi = bias[m];
        float* yrow = Y + (size_t)m * strideY + (size_t)b * Tout;
#pragma unroll
        for (int j = 0; j < 4; j++) {
            int t = tbase + tx * 8 + 2 * j;
            if (t < Tout) {   // Tout is even and t is even -> covers pair
                float2 v;
                v.x = __uint_as_float((unsigned)(acc[i][j] & 0xffffffffULL));
                v.y = __uint_as_float((unsigned)(acc[i][j] >> 32));
                v.x = fmaxf(v.x + bi, 0.f);
                v.y = fmaxf(v.y + bi, 0.f);
                if (actMode) { v.x = fminf(v.x, 6.f); v.y = fminf(v.y, 6.f); }
                *(float2*)&yrow[t] = v;
            }
        }
    }
}

// ---------------- per-channel batch-norm stats (over B*T) -------------------
// Produces scale/shift so that next consumer applies y = scl*x + shf.
__global__ void channel_stats(const float* __restrict__ Y, int N,
                              const float* __restrict__ gam, const float* __restrict__ bet,
                              float* __restrict__ scl, float* __restrict__ shf)
{
    int c = blockIdx.x;
    const float4* p = (const float4*)(Y + (size_t)c * N);
    int n4 = N >> 2;
    float s1 = 0.f, s2 = 0.f;
    for (int i = threadIdx.x; i < n4; i += blockDim.x) {
        float4 v = p[i];
        s1 += v.x + v.y + v.z + v.w;
        s2 += v.x*v.x + v.y*v.y + v.z*v.z + v.w*v.w;
    }
    __shared__ float r1[256], r2[256];
    r1[threadIdx.x] = s1; r2[threadIdx.x] = s2;
    __syncthreads();
    for (int s = 128; s > 0; s >>= 1) {
        if (threadIdx.x < s) {
            r1[threadIdx.x] += r1[threadIdx.x + s];
            r2[threadIdx.x] += r2[threadIdx.x + s];
        }
        __syncthreads();
    }
    if (threadIdx.x == 0) {
        float m   = r1[0] / (float)N;
        float var = r2[0] / (float)N - m * m;
        float inv = rsqrtf(var + 1e-5f);
        float g   = gam ? gam[c] : 1.f;
        float be  = bet ? bet[c] : 0.f;
        float A   = g * inv;
        scl[c] = A;
        shf[c] = be - m * A;
    }
}

// ---------------- stats pooling over time, with folded bn affine ------------
// Pool of (a*x + d): mean' = a*mean + d, std' = |a|*std.
__global__ void pool_stats(const float* __restrict__ A,
                           const float* __restrict__ scl, const float* __restrict__ shf,
                           float* __restrict__ P)
{
    int c = blockIdx.x;  // 0..1499
    int b = blockIdx.y;  // 0..31
    const float* p = A + ((size_t)c * B_ + b) * T3_;
    float s1 = 0.f, s2 = 0.f;
    for (int i = threadIdx.x; i < T3_; i += blockDim.x) {
        float v = p[i]; s1 += v; s2 += v * v;
    }
    __shared__ float r1[128], r2[128];
    r1[threadIdx.x] = s1; r2[threadIdx.x] = s2;
    __syncthreads();
    for (int s = 64; s > 0; s >>= 1) {
        if (threadIdx.x < s) {
            r1[threadIdx.x] += r1[threadIdx.x + s];
            r2[threadIdx.x] += r2[threadIdx.x + s];
        }
        __syncthreads();
    }
    if (threadIdx.x == 0) {
        float m   = r1[0] / (float)T3_;
        float var = (r2[0] - (float)T3_ * m * m) / (float)(T3_ - 1);
        float a = scl[c], d = shf[c];
        P[b * 3000 + c]        = a * m + d;
        P[b * 3000 + 1500 + c] = fabsf(a) * sqrtf(fmaxf(var, 0.f));
    }
}

// ---------------- dense + relu6 (one warp per output) -----------------------
__global__ void dense_relu6(const float* __restrict__ W, const float* __restrict__ bias,
                            const float* __restrict__ X, float* __restrict__ Y,
                            int M, int K)
{
    int gw   = (blockIdx.x * blockDim.x + threadIdx.x) >> 5;
    int lane = threadIdx.x & 31;
    if (gw >= B_ * M) return;
    int b = gw / M, o = gw - b * M;
    const float* w = W + (size_t)o * K;
    const float* x = X + (size_t)b * K;
    float s = 0.f;
    for (int k = lane; k < K; k += 32) s += w[k] * x[k];
#pragma unroll
    for (int off = 16; off; off >>= 1) s += __shfl_xor_sync(0xffffffffu, s, off);
    if (lane == 0) {
        float v = s + bias[o];
        Y[(size_t)b * M + o] = fminf(fmaxf(v, 0.f), 6.f);
    }
}

// ---------------- batch-norm over batch dim (B=32 == warp) ------------------
__global__ void bn_batch(const float* __restrict__ Y, const float* __restrict__ gam,
                         const float* __restrict__ bet, float* __restrict__ Out, int M)
{
    int o    = (blockIdx.x * blockDim.x + threadIdx.x) >> 5;
    int lane = threadIdx.x & 31;
    if (o >= M) return;
    float v  = Y[(size_t)lane * M + o];
    float s1 = v, s2 = v * v;
#pragma unroll
    for (int off = 16; off; off >>= 1) {
        s1 += __shfl_xor_sync(0xffffffffu, s1, off);
        s2 += __shfl_xor_sync(0xffffffffu, s2, off);
    }
    float m   = s1 * (1.f / 32.f);
    float var = s2 * (1.f / 32.f) - m * m;
    float r   = rsqrtf(var + 1e-5f);
    Out[(size_t)lane * M + o] = (v - m) * r * gam[o] + bet[o];
}

// ---------------- launch ----------------------------------------------------
extern "C" void kernel_launch(void* const* d_in, const int* in_sizes, int n_in,
                              void* d_out, int out_size)
{
    const float* x     = (const float*)d_in[0];
    const float* h1_w  = (const float*)d_in[1];
    const float* h1_b  = (const float*)d_in[2];
    const float* h2_w  = (const float*)d_in[3];
    const float* h2_b  = (const float*)d_in[4];
    const float* bn2_g = (const float*)d_in[5];
    const float* bn2_b = (const float*)d_in[6];
    const float* h3_w  = (const float*)d_in[7];
    const float* h3_b  = (const float*)d_in[8];
    const float* bn3_g = (const float*)d_in[9];
    const float* bn3_b = (const float*)d_in[10];
    const float* h4_w  = (const float*)d_in[11];
    const float* h4_b  = (const float*)d_in[12];
    const float* bn4_g = (const float*)d_in[13];
    const float* bn4_b = (const float*)d_in[14];
    const float* h5_w  = (const float*)d_in[15];
    const float* h5_b  = (const float*)d_in[16];
    const float* bn5_g = (const float*)d_in[17];
    const float* bn5_b = (const float*)d_in[18];
    const float* l1_w  = (const float*)d_in[19];
    const float* l1_b  = (const float*)d_in[20];
    const float* bn6_g = (const float*)d_in[21];
    const float* bn6_b = (const float*)d_in[22];
    const float* l2_w  = (const float*)d_in[23];
    const float* l2_b  = (const float*)d_in[24];
    const float* bn7_g = (const float*)d_in[25];
    const float* bn7_b = (const float*)d_in[26];

    float *xT, *a1, *a2, *a3, *a4, *a5, *scl, *shf, *pool, *y1, *y2;
    cudaGetSymbolAddress((void**)&xT,   g_xT);
    cudaGetSymbolAddress((void**)&a1,   g_act1);
    cudaGetSymbolAddress((void**)&a2,   g_act2);
    cudaGetSymbolAddress((void**)&a3,   g_act3);
    cudaGetSymbolAddress((void**)&a4,   g_act4);
    cudaGetSymbolAddress((void**)&a5,   g_act5);
    cudaGetSymbolAddress((void**)&scl,  g_scl);
    cudaGetSymbolAddress((void**)&shf,  g_shf);
    cudaGetSymbolAddress((void**)&pool, g_pool);
    cudaGetSymbolAddress((void**)&y1,   g_y1);
    cudaGetSymbolAddress((void**)&y2,   g_y2);

    const int N1 = B_ * T1_;
    const int N2 = B_ * T2_;
    const int N3 = B_ * T3_;

    transpose_x<<<(B_ * T0_ * 20 + 255) / 256, 256>>>(x, xT);

    // Layer 1: splice(0..4) + h1 + relu ; bn1 stats (no affine) folded forward
    gemm_splice<<<dim3((T1_ + 127) / 128, 4, B_), 256>>>(
        h1_w, h1_b, xT, a1, nullptr, nullptr, 512, 100, 5, 1, T0_, T1_, 0);
    channel_stats<<<512, 256>>>(a1, N1, nullptr, nullptr, scl, shf);

    // Layer 2: (bn1 affine on load) + splice(0,2,4) + h2 + relu
    gemm_splice<<<dim3((T2_ + 127) / 128, 4, B_), 256>>>(
        h2_w, h2_b, a1, a2, scl, shf, 512, 1536, 3, 2, T1_, T2_, 0);
    channel_stats<<<512, 256>>>(a2, N2, bn2_g, bn2_b, scl, shf);

    // Layer 3: (bn2 on load) + splice(0,3,6) + h3 + relu
    gemm_splice<<<dim3((T3_ + 127) / 128, 4, B_), 256>>>(
        h3_w, h3_b, a2, a3, scl, shf, 512, 1536, 3, 3, T2_, T3_, 0);
    channel_stats<<<512, 256>>>(a3, N3, bn3_g, bn3_b, scl, shf);

    // Layer 4: (bn3 on load) + h4 + relu6
    gemm_splice<<<dim3((T3_ + 127) / 128, 4, B_), 256>>>(
        h4_w, h4_b, a3, a4, scl, shf, 512, 512, 1, 0, T3_, T3_, 1);
    channel_stats<<<512, 256>>>(a4, N3, bn4_g, bn4_b, scl, shf);

    // Layer 5: (bn4 on load) + h5 + relu6
    gemm_splice<<<dim3((T3_ + 127) / 128, 12, B_), 256>>>(
        h5_w, h5_b, a4, a5, scl, shf, 1500, 512, 1, 0, T3_, T3_, 1);
    channel_stats<<<1500, 256>>>(a5, N3, bn5_g, bn5_b, scl, shf);

    // Stats pooling with folded bn5 affine -> [B, 3000]
    pool_stats<<<dim3(1500, B_), 128>>>(a5, scl, shf, pool);

    // l1 + relu6 + bn6 (over batch)
    dense_relu6<<<(B_ * 512 * 32 + 255) / 256, 256>>>(l1_w, l1_b, pool, y1, 512, 3000);
    bn_batch<<<(512 * 32 + 255) / 256, 256>>>(y1, bn6_g, bn6_b, y1, 512);

    // l2 + relu6 + bn7 -> output [32, 512]
    dense_relu6<<<(B_ * 512 * 32 + 255) / 256, 256>>>(l2_w, l2_b, y1, y2, 512, 512);
    bn_batch<<<(512 * 32 + 255) / 256, 256>>>(y2, bn7_g, bn7_b, (float*)d_out, 512);
}

// round 5
// speedup vs baseline: 2.0801x; 2.0801x over previous
#include <cuda_runtime.h>
#include <math.h>

#define B_  32
#define T0_ 2048
#define T1_ 2044
#define T2_ 2040
#define T3_ 2034

// ---------------- scratch (device globals; no allocations allowed) ----------
__device__ float g_xT  [20   * B_ * T0_];
__device__ float g_act1[512  * B_ * T1_];
__device__ float g_act2[512  * B_ * T2_];
__device__ float g_act3[512  * B_ * T3_];
__device__ float g_act4[512  * B_ * T3_];
__device__ float g_act5[1500 * B_ * T3_];
__device__ float g_scl [1500];
__device__ float g_shf [1500];
__device__ float g_pool[B_ * 3000];
__device__ float g_y1  [B_ * 512];
__device__ float g_y2  [B_ * 512];

// ---------------- transpose x[b][t][f] -> xT[f][b][t] -----------------------
__global__ void transpose_x(const float* __restrict__ x, float* __restrict__ xT) {
    int idx = blockIdx.x * blockDim.x + threadIdx.x;
    const int total = B_ * T0_ * 20;
    if (idx >= total) return;
    int f = idx % 20;
    int t = (idx / 20) % T0_;
    int b = idx / (20 * T0_);
    xT[((size_t)f * B_ + b) * T0_ + t] = x[idx];
}

// ---------------- TF32 helpers ----------------------------------------------
__device__ __forceinline__ unsigned f2tf32(float v) {
    unsigned r;
    asm("cvt.rna.tf32.f32 %0, %1;" : "=r"(r) : "f"(v));
    return r;
}
// split v into tf32 hi + tf32 lo  (lo = tf32(v - hi))
__device__ __forceinline__ void split_tf32(float v, unsigned &hi, unsigned &lo) {
    hi = f2tf32(v);
    lo = f2tf32(v - __uint_as_float(hi));
}

__device__ __forceinline__ void mma_tf32(float c[4],
                                         unsigned a0, unsigned a1, unsigned a2, unsigned a3,
                                         unsigned b0, unsigned b1) {
    asm("mma.sync.aligned.m16n8k8.row.col.f32.tf32.tf32.f32 "
        "{%0,%1,%2,%3}, {%4,%5,%6,%7}, {%8,%9}, {%0,%1,%2,%3};"
        : "+f"(c[0]), "+f"(c[1]), "+f"(c[2]), "+f"(c[3])
        : "r"(a0), "r"(a1), "r"(a2), "r"(a3), "r"(b0), "r"(b1));
}

// ---------------- fused (bn-affine on input) + splice + 1x1 conv GEMM --------
// Y[m][b][t] = act( sum_k W[m][k] * (sA[f]*X[f][b][t+off] + sB[f]) + bias[m] )
// 3xTF32 split-precision tensor-core GEMM: block 128x128x16, 8 warps, warp 64x32.
#define TBM 128
#define TBN 128
#define TBK 16

__global__ __launch_bounds__(256, 2)
void gemm_splice(const float* __restrict__ W, const float* __restrict__ bias,
                 const float* __restrict__ X, float* __restrict__ Y,
                 const float* __restrict__ scl, const float* __restrict__ shf,
                 int M, int K, int C, int offStride,
                 int Tin, int Tout, int actMode)
{
    __shared__ unsigned AsH[TBK][TBM + 4];
    __shared__ unsigned AsL[TBK][TBM + 4];
    __shared__ unsigned BsH[TBK][TBN + 4];
    __shared__ unsigned BsL[TBK][TBN + 4];

    const int b     = blockIdx.z;
    const int m0    = blockIdx.y * TBM;
    const int tbase = blockIdx.x * TBN;
    const int tid   = threadIdx.x;

    const int lane  = tid & 31;
    const int warp  = tid >> 5;
    const int g     = lane >> 2;        // 0..7
    const int tg    = lane & 3;         // 0..3
    const int wm    = (warp & 1) * 64;
    const int wn    = (warp >> 1) * 32;

    const float* Xb = X + (size_t)b * Tin;

    float acc[4][4][4];
#pragma unroll
    for (int mi = 0; mi < 4; mi++)
#pragma unroll
        for (int ni = 0; ni < 4; ni++)
#pragma unroll
            for (int r = 0; r < 4; r++) acc[mi][ni][r] = 0.f;

    const int aRow  = tid >> 1;
    const int aCol0 = (tid & 1) * 8;
    const int bRow  = tid >> 4;
    const int bCol0 = (tid & 15) * 8;

    for (int k0 = 0; k0 < K; k0 += TBK) {
        // ---- load W tile (zero-padded), split to tf32 hi/lo ----
        {
            int m = m0 + aRow;
#pragma unroll
            for (int j = 0; j < 8; j++) {
                int k = k0 + aCol0 + j;
                float v = (k < K && m < M) ? W[(size_t)m * K + k] : 0.f;
                unsigned h, l; split_tf32(v, h, l);
                AsH[aCol0 + j][aRow] = h;
                AsL[aCol0 + j][aRow] = l;
            }
        }
        // ---- load X tile with splice gather + folded bn affine, split ----
        {
            int k = k0 + bRow;
            bool kv = (k < K);
            int f = 0, off = 0;
            if (kv) { f = k / C; off = (k - f * C) * offStride; }
            float sA = 1.f, sB = 0.f;
            if (kv && scl) { sA = scl[f]; sB = shf[f]; }
            const float* src = Xb + (size_t)f * (B_ * (size_t)Tin) + off + tbase + bCol0;
#pragma unroll
            for (int j = 0; j < 8; j++) {
                int t = tbase + bCol0 + j;
                float v = (kv && t < Tout) ? fmaf(src[j], sA, sB) : 0.f;
                unsigned h, l; split_tf32(v, h, l);
                BsH[bRow][bCol0 + j] = h;
                BsL[bRow][bCol0 + j] = l;
            }
        }
        __syncthreads();

#pragma unroll
        for (int kk = 0; kk < TBK; kk += 8) {
            unsigned af[4][4], bfh[4][2], bfx[4][2];
            // --- A_hi, B_hi fragments; product hi*hi ---
#pragma unroll
            for (int mi = 0; mi < 4; mi++) {
                int m = wm + mi * 16 + g;
                af[mi][0] = AsH[kk + tg    ][m];
                af[mi][1] = AsH[kk + tg    ][m + 8];
                af[mi][2] = AsH[kk + tg + 4][m];
                af[mi][3] = AsH[kk + tg + 4][m + 8];
            }
#pragma unroll
            for (int ni = 0; ni < 4; ni++) {
                int n = wn + ni * 8 + g;
                bfh[ni][0] = BsH[kk + tg    ][n];
                bfh[ni][1] = BsH[kk + tg + 4][n];
            }
#pragma unroll
            for (int mi = 0; mi < 4; mi++)
#pragma unroll
                for (int ni = 0; ni < 4; ni++)
                    mma_tf32(acc[mi][ni], af[mi][0], af[mi][1], af[mi][2], af[mi][3],
                             bfh[ni][0], bfh[ni][1]);
            // --- product hi*lo ---
#pragma unroll
            for (int ni = 0; ni < 4; ni++) {
                int n = wn + ni * 8 + g;
                bfx[ni][0] = BsL[kk + tg    ][n];
                bfx[ni][1] = BsL[kk + tg + 4][n];
            }
#pragma unroll
            for (int mi = 0; mi < 4; mi++)
#pragma unroll
                for (int ni = 0; ni < 4; ni++)
                    mma_tf32(acc[mi][ni], af[mi][0], af[mi][1], af[mi][2], af[mi][3],
                             bfx[ni][0], bfx[ni][1]);
            // --- product lo*hi (A_lo overwrites af) ---
#pragma unroll
            for (int mi = 0; mi < 4; mi++) {
                int m = wm + mi * 16 + g;
                af[mi][0] = AsL[kk + tg    ][m];
                af[mi][1] = AsL[kk + tg    ][m + 8];
                af[mi][2] = AsL[kk + tg + 4][m];
                af[mi][3] = AsL[kk + tg + 4][m + 8];
            }
#pragma unroll
            for (int mi = 0; mi < 4; mi++)
#pragma unroll
                for (int ni = 0; ni < 4; ni++)
                    mma_tf32(acc[mi][ni], af[mi][0], af[mi][1], af[mi][2], af[mi][3],
                             bfh[ni][0], bfh[ni][1]);
        }
        __syncthreads();
    }

    // ---- epilogue: bias + activation, write [M][B][Tout] ----
    const size_t strideY = (size_t)B_ * Tout;
#pragma unroll
    for (int mi = 0; mi < 4; mi++) {
        int mA = m0 + wm + mi * 16 + g;
        int mB = mA + 8;
        float biA = (mA < M) ? bias[mA] : 0.f;
        float biB = (mB < M) ? bias[mB] : 0.f;
#pragma unroll
        for (int ni = 0; ni < 4; ni++) {
            int t = tbase + wn + ni * 8 + tg * 2;
            if (t >= Tout) continue;
            if (mA < M) {
                float2 v;
                v.x = fmaxf(acc[mi][ni][0] + biA, 0.f);
                v.y = fmaxf(acc[mi][ni][1] + biA, 0.f);
                if (actMode) { v.x = fminf(v.x, 6.f); v.y = fminf(v.y, 6.f); }
                *(float2*)&Y[(size_t)mA * strideY + (size_t)b * Tout + t] = v;
            }
            if (mB < M) {
                float2 v;
                v.x = fmaxf(acc[mi][ni][2] + biB, 0.f);
                v.y = fmaxf(acc[mi][ni][3] + biB, 0.f);
                if (actMode) { v.x = fminf(v.x, 6.f); v.y = fminf(v.y, 6.f); }
                *(float2*)&Y[(size_t)mB * strideY + (size_t)b * Tout + t] = v;
            }
        }
    }
}

// ---------------- per-channel batch-norm stats (over B*T) -------------------
__global__ void channel_stats(const float* __restrict__ Y, int N,
                              const float* __restrict__ gam, const float* __restrict__ bet,
                              float* __restrict__ scl, float* __restrict__ shf)
{
    int c = blockIdx.x;
    const float4* p = (const float4*)(Y + (size_t)c * N);
    int n4 = N >> 2;
    float s1 = 0.f, s2 = 0.f;
    for (int i = threadIdx.x; i < n4; i += blockDim.x) {
        float4 v = p[i];
        s1 += v.x + v.y + v.z + v.w;
        s2 += v.x*v.x + v.y*v.y + v.z*v.z + v.w*v.w;
    }
    __shared__ float r1[256], r2[256];
    r1[threadIdx.x] = s1; r2[threadIdx.x] = s2;
    __syncthreads();
    for (int s = 128; s > 0; s >>= 1) {
        if (threadIdx.x < s) {
            r1[threadIdx.x] += r1[threadIdx.x + s];
            r2[threadIdx.x] += r2[threadIdx.x + s];
        }
        __syncthreads();
    }
    if (threadIdx.x == 0) {
        float m   = r1[0] / (float)N;
        float var = r2[0] / (float)N - m * m;
        float inv = rsqrtf(var + 1e-5f);
        float g   = gam ? gam[c] : 1.f;
        float be  = bet ? bet[c] : 0.f;
        float A   = g * inv;
        scl[c] = A;
        shf[c] = be - m * A;
    }
}

// ---------------- stats pooling over time, with folded bn affine ------------
__global__ void pool_stats(const float* __restrict__ A,
                           const float* __restrict__ scl, const float* __restrict__ shf,
                           float* __restrict__ P)
{
    int c = blockIdx.x;
    int b = blockIdx.y;
    const float* p = A + ((size_t)c * B_ + b) * T3_;
    float s1 = 0.f, s2 = 0.f;
    for (int i = threadIdx.x; i < T3_; i += blockDim.x) {
        float v = p[i]; s1 += v; s2 += v * v;
    }
    __shared__ float r1[128], r2[128];
    r1[threadIdx.x] = s1; r2[threadIdx.x] = s2;
    __syncthreads();
    for (int s = 64; s > 0; s >>= 1) {
        if (threadIdx.x < s) {
            r1[threadIdx.x] += r1[threadIdx.x + s];
            r2[threadIdx.x] += r2[threadIdx.x + s];
        }
        __syncthreads();
    }
    if (threadIdx.x == 0) {
        float m   = r1[0] / (float)T3_;
        float var = (r2[0] - (float)T3_ * m * m) / (float)(T3_ - 1);
        float a = scl[c], d = shf[c];
        P[b * 3000 + c]        = a * m + d;
        P[b * 3000 + 1500 + c] = fabsf(a) * sqrtf(fmaxf(var, 0.f));
    }
}

// ---------------- dense + relu6 (one warp per output) -----------------------
__global__ void dense_relu6(const float* __restrict__ W, const float* __restrict__ bias,
                            const float* __restrict__ X, float* __restrict__ Y,
                            int M, int K)
{
    int gw   = (blockIdx.x * blockDim.x + threadIdx.x) >> 5;
    int lane = threadIdx.x & 31;
    if (gw >= B_ * M) return;
    int b = gw / M, o = gw - b * M;
    const float* w = W + (size_t)o * K;
    const float* x = X + (size_t)b * K;
    float s = 0.f;
    for (int k = lane; k < K; k += 32) s += w[k] * x[k];
#pragma unroll
    for (int off = 16; off; off >>= 1) s += __shfl_xor_sync(0xffffffffu, s, off);
    if (lane == 0) {
        float v = s + bias[o];
        Y[(size_t)b * M + o] = fminf(fmaxf(v, 0.f), 6.f);
    }
}

// ---------------- batch-norm over batch dim (B=32 == warp) ------------------
__global__ void bn_batch(const float* __restrict__ Y, const float* __restrict__ gam,
                         const float* __restrict__ bet, float* __restrict__ Out, int M)
{
    int o    = (blockIdx.x * blockDim.x + threadIdx.x) >> 5;
    int lane = threadIdx.x & 31;
    if (o >= M) return;
    float v  = Y[(size_t)lane * M + o];
    float s1 = v, s2 = v * v;
#pragma unroll
    for (int off = 16; off; off >>= 1) {
        s1 += __shfl_xor_sync(0xffffffffu, s1, off);
        s2 += __shfl_xor_sync(0xffffffffu, s2, off);
    }
    float m   = s1 * (1.f / 32.f);
    float var = s2 * (1.f / 32.f) - m * m;
    float r   = rsqrtf(var + 1e-5f);
    Out[(size_t)lane * M + o] = (v - m) * r * gam[o] + bet[o];
}

// ---------------- launch ----------------------------------------------------
extern "C" void kernel_launch(void* const* d_in, const int* in_sizes, int n_in,
                              void* d_out, int out_size)
{
    const float* x     = (const float*)d_in[0];
    const float* h1_w  = (const float*)d_in[1];
    const float* h1_b  = (const float*)d_in[2];
    const float* h2_w  = (const float*)d_in[3];
    const float* h2_b  = (const float*)d_in[4];
    const float* bn2_g = (const float*)d_in[5];
    const float* bn2_b = (const float*)d_in[6];
    const float* h3_w  = (const float*)d_in[7];
    const float* h3_b  = (const float*)d_in[8];
    const float* bn3_g = (const float*)d_in[9];
    const float* bn3_b = (const float*)d_in[10];
    const float* h4_w  = (const float*)d_in[11];
    const float* h4_b  = (const float*)d_in[12];
    const float* bn4_g = (const float*)d_in[13];
    const float* bn4_b = (const float*)d_in[14];
    const float* h5_w  = (const float*)d_in[15];
    const float* h5_b  = (const float*)d_in[16];
    const float* bn5_g = (const float*)d_in[17];
    const float* bn5_b = (const float*)d_in[18];
    const float* l1_w  = (const float*)d_in[19];
    const float* l1_b  = (const float*)d_in[20];
    const float* bn6_g = (const float*)d_in[21];
    const float* bn6_b = (const float*)d_in[22];
    const float* l2_w  = (const float*)d_in[23];
    const float* l2_b  = (const float*)d_in[24];
    const float* bn7_g = (const float*)d_in[25];
    const float* bn7_b = (const float*)d_in[26];

    float *xT, *a1, *a2, *a3, *a4, *a5, *scl, *shf, *pool, *y1, *y2;
    cudaGetSymbolAddress((void**)&xT,   g_xT);
    cudaGetSymbolAddress((void**)&a1,   g_act1);
    cudaGetSymbolAddress((void**)&a2,   g_act2);
    cudaGetSymbolAddress((void**)&a3,   g_act3);
    cudaGetSymbolAddress((void**)&a4,   g_act4);
    cudaGetSymbolAddress((void**)&a5,   g_act5);
    cudaGetSymbolAddress((void**)&scl,  g_scl);
    cudaGetSymbolAddress((void**)&shf,  g_shf);
    cudaGetSymbolAddress((void**)&pool, g_pool);
    cudaGetSymbolAddress((void**)&y1,   g_y1);
    cudaGetSymbolAddress((void**)&y2,   g_y2);

    const int N1 = B_ * T1_;
    const int N2 = B_ * T2_;
    const int N3 = B_ * T3_;

    transpose_x<<<(B_ * T0_ * 20 + 255) / 256, 256>>>(x, xT);

    gemm_splice<<<dim3((T1_ + 127) / 128, 4, B_), 256>>>(
        h1_w, h1_b, xT, a1, nullptr, nullptr, 512, 100, 5, 1, T0_, T1_, 0);
    channel_stats<<<512, 256>>>(a1, N1, nullptr, nullptr, scl, shf);

    gemm_splice<<<dim3((T2_ + 127) / 128, 4, B_), 256>>>(
        h2_w, h2_b, a1, a2, scl, shf, 512, 1536, 3, 2, T1_, T2_, 0);
    channel_stats<<<512, 256>>>(a2, N2, bn2_g, bn2_b, scl, shf);

    gemm_splice<<<dim3((T3_ + 127) / 128, 4, B_), 256>>>(
        h3_w, h3_b, a2, a3, scl, shf, 512, 1536, 3, 3, T2_, T3_, 0);
    channel_stats<<<512, 256>>>(a3, N3, bn3_g, bn3_b, scl, shf);

    gemm_splice<<<dim3((T3_ + 127) / 128, 4, B_), 256>>>(
        h4_w, h4_b, a3, a4, scl, shf, 512, 512, 1, 0, T3_, T3_, 1);
    channel_stats<<<512, 256>>>(a4, N3, bn4_g, bn4_b, scl, shf);

    gemm_splice<<<dim3((T3_ + 127) / 128, 12, B_), 256>>>(
        h5_w, h5_b, a4, a5, scl, shf, 1500, 512, 1, 0, T3_, T3_, 1);
    channel_stats<<<1500, 256>>>(a5, N3, bn5_g, bn5_b, scl, shf);

    pool_stats<<<dim3(1500, B_), 128>>>(a5, scl, shf, pool);

    dense_relu6<<<(B_ * 512 * 32 + 255) / 256, 256>>>(l1_w, l1_b, pool, y1, 512, 3000);
    bn_batch<<<(512 * 32 + 255) / 256, 256>>>(y1, bn6_g, bn6_b, y1, 512);

    dense_relu6<<<(B_ * 512 * 32 + 255) / 256, 256>>>(l2_w, l2_b, y1, y2, 512, 512);
    bn_batch<<<(512 * 32 + 255) / 256, 256>>>(y2, bn7_g, bn7_b, (float*)d_out, 512);
}

// round 6
// speedup vs baseline: 2.3091x; 1.1101x over previous
#include <cuda_runtime.h>
#include <math.h>

#define B_  32
#define T0_ 2048
#define T1_ 2044
#define T2_ 2040
#define T3_ 2034

// ---------------- scratch (device globals; no allocations allowed) ----------
__device__ float g_xT  [20   * B_ * T0_];
__device__ float g_act1[512  * B_ * T1_];
__device__ float g_act2[512  * B_ * T2_];
__device__ float g_act3[512  * B_ * T3_];
__device__ float g_act4[512  * B_ * T3_];
__device__ float g_act5[1500 * B_ * T3_];
__device__ float g_scl [1500];
__device__ float g_shf [1500];
__device__ float g_pool[B_ * 3000];
__device__ float g_y1  [B_ * 512];
__device__ float g_y2  [B_ * 512];

// ---------------- transpose x[b][t][f] -> xT[f][b][t] -----------------------
__global__ void transpose_x(const float* __restrict__ x, float* __restrict__ xT) {
    int idx = blockIdx.x * blockDim.x + threadIdx.x;
    const int total = B_ * T0_ * 20;
    if (idx >= total) return;
    int f = idx % 20;
    int t = (idx / 20) % T0_;
    int b = idx / (20 * T0_);
    xT[((size_t)f * B_ + b) * T0_ + t] = x[idx];
}

// ---------------- TF32 helpers ----------------------------------------------
__device__ __forceinline__ unsigned f2tf32(float v) {
    unsigned r;
    asm("cvt.rna.tf32.f32 %0, %1;" : "=r"(r) : "f"(v));
    return r;
}
__device__ __forceinline__ void split_tf32(float v, unsigned &hi, unsigned &lo) {
    hi = f2tf32(v);
    lo = f2tf32(v - __uint_as_float(hi));
}

__device__ __forceinline__ void mma_tf32(float c[4],
                                         unsigned a0, unsigned a1, unsigned a2, unsigned a3,
                                         unsigned b0, unsigned b1) {
    asm("mma.sync.aligned.m16n8k8.row.col.f32.tf32.tf32.f32 "
        "{%0,%1,%2,%3}, {%4,%5,%6,%7}, {%8,%9}, {%0,%1,%2,%3};"
        : "+f"(c[0]), "+f"(c[1]), "+f"(c[2]), "+f"(c[3])
        : "r"(a0), "r"(a1), "r"(a2), "r"(a3), "r"(b0), "r"(b1));
}

// ---------------- fused (bn-affine on input) + splice + 1x1 conv GEMM --------
// 3xTF32 split-precision tensor-core GEMM: block 128x128x16, 8 warps, warp 64x32.
// Shared rows padded to +8 words => fragment LDS bank = 8*tg+g : conflict-free.
#define TBM 128
#define TBN 128
#define TBK 16
#define PAD 8

__global__ __launch_bounds__(256, 2)
void gemm_splice(const float* __restrict__ W, const float* __restrict__ bias,
                 const float* __restrict__ X, float* __restrict__ Y,
                 const float* __restrict__ scl, const float* __restrict__ shf,
                 int M, int K, int C, int offStride,
                 int Tin, int Tout, int actMode)
{
    __shared__ unsigned AsH[TBK][TBM + PAD];
    __shared__ unsigned AsL[TBK][TBM + PAD];
    __shared__ unsigned BsH[TBK][TBN + PAD];
    __shared__ unsigned BsL[TBK][TBN + PAD];

    const int b     = blockIdx.z;
    const int m0    = blockIdx.y * TBM;
    const int tbase = blockIdx.x * TBN;
    const int tid   = threadIdx.x;

    const int lane  = tid & 31;
    const int warp  = tid >> 5;
    const int g     = lane >> 2;        // 0..7
    const int tg    = lane & 3;         // 0..3
    const int wm    = (warp & 1) * 64;
    const int wn    = (warp >> 1) * 32;

    const float* Xb = X + (size_t)b * Tin;

    float acc[4][4][4];
#pragma unroll
    for (int mi = 0; mi < 4; mi++)
#pragma unroll
        for (int ni = 0; ni < 4; ni++)
#pragma unroll
            for (int r = 0; r < 4; r++) acc[mi][ni][r] = 0.f;

    const int aRow  = tid >> 1;
    const int aCol0 = (tid & 1) * 8;
    const int bRow  = tid >> 4;
    const int bCol0 = (tid & 15) * 8;

    for (int k0 = 0; k0 < K; k0 += TBK) {
        // ---- load W tile (zero-padded), split to tf32 hi/lo ----
        {
            int m = m0 + aRow;
#pragma unroll
            for (int j = 0; j < 8; j++) {
                int k = k0 + aCol0 + j;
                float v = (k < K && m < M) ? W[(size_t)m * K + k] : 0.f;
                unsigned h, l; split_tf32(v, h, l);
                AsH[aCol0 + j][aRow] = h;
                AsL[aCol0 + j][aRow] = l;
            }
        }
        // ---- load X tile with splice gather + folded bn affine, split ----
        {
            int k = k0 + bRow;
            bool kv = (k < K);
            int f = 0, off = 0;
            if (kv) { f = k / C; off = (k - f * C) * offStride; }
            float sA = 1.f, sB = 0.f;
            if (kv && scl) { sA = scl[f]; sB = shf[f]; }
            const float* src = Xb + (size_t)f * (B_ * (size_t)Tin) + off + tbase + bCol0;
            unsigned vh[8], vl[8];
#pragma unroll
            for (int j = 0; j < 8; j++) {
                int t = tbase + bCol0 + j;
                float v = (kv && t < Tout) ? fmaf(src[j], sA, sB) : 0.f;
                split_tf32(v, vh[j], vl[j]);
            }
            // vectorized 16B stores (aligned: bCol0 multiple of 8 words, row pitch 544B)
            *(uint4*)&BsH[bRow][bCol0]     = make_uint4(vh[0], vh[1], vh[2], vh[3]);
            *(uint4*)&BsH[bRow][bCol0 + 4] = make_uint4(vh[4], vh[5], vh[6], vh[7]);
            *(uint4*)&BsL[bRow][bCol0]     = make_uint4(vl[0], vl[1], vl[2], vl[3]);
            *(uint4*)&BsL[bRow][bCol0 + 4] = make_uint4(vl[4], vl[5], vl[6], vl[7]);
        }
        __syncthreads();

#pragma unroll
        for (int kk = 0; kk < TBK; kk += 8) {
            unsigned af[4][4], bfh[4][2], bfx[4][2];
            // --- A_hi, B_hi fragments; product hi*hi ---
#pragma unroll
            for (int mi = 0; mi < 4; mi++) {
                int m = wm + mi * 16 + g;
                af[mi][0] = AsH[kk + tg    ][m];
                af[mi][1] = AsH[kk + tg    ][m + 8];
                af[mi][2] = AsH[kk + tg + 4][m];
                af[mi][3] = AsH[kk + tg + 4][m + 8];
            }
#pragma unroll
            for (int ni = 0; ni < 4; ni++) {
                int n = wn + ni * 8 + g;
                bfh[ni][0] = BsH[kk + tg    ][n];
                bfh[ni][1] = BsH[kk + tg + 4][n];
            }
#pragma unroll
            for (int mi = 0; mi < 4; mi++)
#pragma unroll
                for (int ni = 0; ni < 4; ni++)
                    mma_tf32(acc[mi][ni], af[mi][0], af[mi][1], af[mi][2], af[mi][3],
                             bfh[ni][0], bfh[ni][1]);
            // --- product hi*lo ---
#pragma unroll
            for (int ni = 0; ni < 4; ni++) {
                int n = wn + ni * 8 + g;
                bfx[ni][0] = BsL[kk + tg    ][n];
                bfx[ni][1] = BsL[kk + tg + 4][n];
            }
#pragma unroll
            for (int mi = 0; mi < 4; mi++)
#pragma unroll
                for (int ni = 0; ni < 4; ni++)
                    mma_tf32(acc[mi][ni], af[mi][0], af[mi][1], af[mi][2], af[mi][3],
                             bfx[ni][0], bfx[ni][1]);
            // --- product lo*hi (A_lo overwrites af) ---
#pragma unroll
            for (int mi = 0; mi < 4; mi++) {
                int m = wm + mi * 16 + g;
                af[mi][0] = AsL[kk + tg    ][m];
                af[mi][1] = AsL[kk + tg    ][m + 8];
                af[mi][2] = AsL[kk + tg + 4][m];
                af[mi][3] = AsL[kk + tg + 4][m + 8];
            }
#pragma unroll
            for (int mi = 0; mi < 4; mi++)
#pragma unroll
                for (int ni = 0; ni < 4; ni++)
                    mma_tf32(acc[mi][ni], af[mi][0], af[mi][1], af[mi][2], af[mi][3],
                             bfh[ni][0], bfh[ni][1]);
        }
        __syncthreads();
    }

    // ---- epilogue: bias + activation, write [M][B][Tout] ----
    const size_t strideY = (size_t)B_ * Tout;
#pragma unroll
    for (int mi = 0; mi < 4; mi++) {
        int mA = m0 + wm + mi * 16 + g;
        int mB = mA + 8;
        float biA = (mA < M) ? bias[mA] : 0.f;
        float biB = (mB < M) ? bias[mB] : 0.f;
#pragma unroll
        for (int ni = 0; ni < 4; ni++) {
            int t = tbase + wn + ni * 8 + tg * 2;
            if (t >= Tout) continue;
            if (mA < M) {
                float2 v;
                v.x = fmaxf(acc[mi][ni][0] + biA, 0.f);
                v.y = fmaxf(acc[mi][ni][1] + biA, 0.f);
                if (actMode) { v.x = fminf(v.x, 6.f); v.y = fminf(v.y, 6.f); }
                *(float2*)&Y[(size_t)mA * strideY + (size_t)b * Tout + t] = v;
            }
            if (mB < M) {
                float2 v;
                v.x = fmaxf(acc[mi][ni][2] + biB, 0.f);
                v.y = fmaxf(acc[mi][ni][3] + biB, 0.f);
                if (actMode) { v.x = fminf(v.x, 6.f); v.y = fminf(v.y, 6.f); }
                *(float2*)&Y[(size_t)mB * strideY + (size_t)b * Tout + t] = v;
            }
        }
    }
}

// ---------------- per-channel batch-norm stats (over B*T) -------------------
__global__ void channel_stats(const float* __restrict__ Y, int N,
                              const float* __restrict__ gam, const float* __restrict__ bet,
                              float* __restrict__ scl, float* __restrict__ shf)
{
    int c = blockIdx.x;
    const float4* p = (const float4*)(Y + (size_t)c * N);
    int n4 = N >> 2;
    float s1 = 0.f, s2 = 0.f;
    for (int i = threadIdx.x; i < n4; i += blockDim.x) {
        float4 v = p[i];
        s1 += v.x + v.y + v.z + v.w;
        s2 += v.x*v.x + v.y*v.y + v.z*v.z + v.w*v.w;
    }
    __shared__ float r1[256], r2[256];
    r1[threadIdx.x] = s1; r2[threadIdx.x] = s2;
    __syncthreads();
    for (int s = 128; s > 0; s >>= 1) {
        if (threadIdx.x < s) {
            r1[threadIdx.x] += r1[threadIdx.x + s];
            r2[threadIdx.x] += r2[threadIdx.x + s];
        }
        __syncthreads();
    }
    if (threadIdx.x == 0) {
        float m   = r1[0] / (float)N;
        float var = r2[0] / (float)N - m * m;
        float inv = rsqrtf(var + 1e-5f);
        float g   = gam ? gam[c] : 1.f;
        float be  = bet ? bet[c] : 0.f;
        float A   = g * inv;
        scl[c] = A;
        shf[c] = be - m * A;
    }
}

// ---------------- stats pooling over time, with folded bn affine ------------
__global__ void pool_stats(const float* __restrict__ A,
                           const float* __restrict__ scl, const float* __restrict__ shf,
                           float* __restrict__ P)
{
    int c = blockIdx.x;
    int b = blockIdx.y;
    const float* p = A + ((size_t)c * B_ + b) * T3_;
    float s1 = 0.f, s2 = 0.f;
    for (int i = threadIdx.x; i < T3_; i += blockDim.x) {
        float v = p[i]; s1 += v; s2 += v * v;
    }
    __shared__ float r1[128], r2[128];
    r1[threadIdx.x] = s1; r2[threadIdx.x] = s2;
    __syncthreads();
    for (int s = 64; s > 0; s >>= 1) {
        if (threadIdx.x < s) {
            r1[threadIdx.x] += r1[threadIdx.x + s];
            r2[threadIdx.x] += r2[threadIdx.x + s];
        }
        __syncthreads();
    }
    if (threadIdx.x == 0) {
        float m   = r1[0] / (float)T3_;
        float var = (r2[0] - (float)T3_ * m * m) / (float)(T3_ - 1);
        float a = scl[c], d = shf[c];
        P[b * 3000 + c]        = a * m + d;
        P[b * 3000 + 1500 + c] = fabsf(a) * sqrtf(fmaxf(var, 0.f));
    }
}

// ---------------- dense + relu6 (one warp per output) -----------------------
__global__ void dense_relu6(const float* __restrict__ W, const float* __restrict__ bias,
                            const float* __restrict__ X, float* __restrict__ Y,
                            int M, int K)
{
    int gw   = (blockIdx.x * blockDim.x + threadIdx.x) >> 5;
    int lane = threadIdx.x & 31;
    if (gw >= B_ * M) return;
    int b = gw / M, o = gw - b * M;
    const float* w = W + (size_t)o * K;
    const float* x = X + (size_t)b * K;
    float s = 0.f;
    for (int k = lane; k < K; k += 32) s += w[k] * x[k];
#pragma unroll
    for (int off = 16; off; off >>= 1) s += __shfl_xor_sync(0xffffffffu, s, off);
    if (lane == 0) {
        float v = s + bias[o];
        Y[(size_t)b * M + o] = fminf(fmaxf(v, 0.f), 6.f);
    }
}

// ---------------- batch-norm over batch dim (B=32 == warp) ------------------
__global__ void bn_batch(const float* __restrict__ Y, const float* __restrict__ gam,
                         const float* __restrict__ bet, float* __restrict__ Out, int M)
{
    int o    = (blockIdx.x * blockDim.x + threadIdx.x) >> 5;
    int lane = threadIdx.x & 31;
    if (o >= M) return;
    float v  = Y[(size_t)lane * M + o];
    float s1 = v, s2 = v * v;
#pragma unroll
    for (int off = 16; off; off >>= 1) {
        s1 += __shfl_xor_sync(0xffffffffu, s1, off);
        s2 += __shfl_xor_sync(0xffffffffu, s2, off);
    }
    float m   = s1 * (1.f / 32.f);
    float var = s2 * (1.f / 32.f) - m * m;
    float r   = rsqrtf(var + 1e-5f);
    Out[(size_t)lane * M + o] = (v - m) * r * gam[o] + bet[o];
}

// ---------------- launch ----------------------------------------------------
extern "C" void kernel_launch(void* const* d_in, const int* in_sizes, int n_in,
                              void* d_out, int out_size)
{
    const float* x     = (const float*)d_in[0];
    const float* h1_w  = (const float*)d_in[1];
    const float* h1_b  = (const float*)d_in[2];
    const float* h2_w  = (const float*)d_in[3];
    const float* h2_b  = (const float*)d_in[4];
    const float* bn2_g = (const float*)d_in[5];
    const float* bn2_b = (const float*)d_in[6];
    const float* h3_w  = (const float*)d_in[7];
    const float* h3_b  = (const float*)d_in[8];
    const float* bn3_g = (const float*)d_in[9];
    const float* bn3_b = (const float*)d_in[10];
    const float* h4_w  = (const float*)d_in[11];
    const float* h4_b  = (const float*)d_in[12];
    const float* bn4_g = (const float*)d_in[13];
    const float* bn4_b = (const float*)d_in[14];
    const float* h5_w  = (const float*)d_in[15];
    const float* h5_b  = (const float*)d_in[16];
    const float* bn5_g = (const float*)d_in[17];
    const float* bn5_b = (const float*)d_in[18];
    const float* l1_w  = (const float*)d_in[19];
    const float* l1_b  = (const float*)d_in[20];
    const float* bn6_g = (const float*)d_in[21];
    const float* bn6_b = (const float*)d_in[22];
    const float* l2_w  = (const float*)d_in[23];
    const float* l2_b  = (const float*)d_in[24];
    const float* bn7_g = (const float*)d_in[25];
    const float* bn7_b = (const float*)d_in[26];

    float *xT, *a1, *a2, *a3, *a4, *a5, *scl, *shf, *pool, *y1, *y2;
    cudaGetSymbolAddress((void**)&xT,   g_xT);
    cudaGetSymbolAddress((void**)&a1,   g_act1);
    cudaGetSymbolAddress((void**)&a2,   g_act2);
    cudaGetSymbolAddress((void**)&a3,   g_act3);
    cudaGetSymbolAddress((void**)&a4,   g_act4);
    cudaGetSymbolAddress((void**)&a5,   g_act5);
    cudaGetSymbolAddress((void**)&scl,  g_scl);
    cudaGetSymbolAddress((void**)&shf,  g_shf);
    cudaGetSymbolAddress((void**)&pool, g_pool);
    cudaGetSymbolAddress((void**)&y1,   g_y1);
    cudaGetSymbolAddress((void**)&y2,   g_y2);

    const int N1 = B_ * T1_;
    const int N2 = B_ * T2_;
    const int N3 = B_ * T3_;

    transpose_x<<<(B_ * T0_ * 20 + 255) / 256, 256>>>(x, xT);

    gemm_splice<<<dim3((T1_ + 127) / 128, 4, B_), 256>>>(
        h1_w, h1_b, xT, a1, nullptr, nullptr, 512, 100, 5, 1, T0_, T1_, 0);
    channel_stats<<<512, 256>>>(a1, N1, nullptr, nullptr, scl, shf);

    gemm_splice<<<dim3((T2_ + 127) / 128, 4, B_), 256>>>(
        h2_w, h2_b, a1, a2, scl, shf, 512, 1536, 3, 2, T1_, T2_, 0);
    channel_stats<<<512, 256>>>(a2, N2, bn2_g, bn2_b, scl, shf);

    gemm_splice<<<dim3((T3_ + 127) / 128, 4, B_), 256>>>(
        h3_w, h3_b, a2, a3, scl, shf, 512, 1536, 3, 3, T2_, T3_, 0);
    channel_stats<<<512, 256>>>(a3, N3, bn3_g, bn3_b, scl, shf);

    gemm_splice<<<dim3((T3_ + 127) / 128, 4, B_), 256>>>(
        h4_w, h4_b, a3, a4, scl, shf, 512, 512, 1, 0, T3_, T3_, 1);
    channel_stats<<<512, 256>>>(a4, N3, bn4_g, bn4_b, scl, shf);

    gemm_splice<<<dim3((T3_ + 127) / 128, 12, B_), 256>>>(
        h5_w, h5_b, a4, a5, scl, shf, 1500, 512, 1, 0, T3_, T3_, 1);
    channel_stats<<<1500, 256>>>(a5, N3, bn5_g, bn5_b, scl, shf);

    pool_stats<<<dim3(1500, B_), 128>>>(a5, scl, shf, pool);

    dense_relu6<<<(B_ * 512 * 32 + 255) / 256, 256>>>(l1_w, l1_b, pool, y1, 512, 3000);
    bn_batch<<<(512 * 32 + 255) / 256, 256>>>(y1, bn6_g, bn6_b, y1, 512);

    dense_relu6<<<(B_ * 512 * 32 + 255) / 256, 256>>>(l2_w, l2_b, y1, y2, 512, 512);
    bn_batch<<<(512 * 32 + 255) / 256, 256>>>(y2, bn7_g, bn7_b, (float*)d_out, 512);
}